// round 1
// baseline (speedup 1.0000x reference)
#include <cuda_runtime.h>

// E = exp_se3(w, v, theta), 4x4 row-major, computed once on device.
__device__ float g_E[16];

__global__ void setup_E_kernel(const float* __restrict__ w,
                               const float* __restrict__ v,
                               const float* __restrict__ theta_p) {
    if (threadIdx.x != 0 || blockIdx.x != 0) return;
    float wx = w[0], wy = w[1], wz = w[2];
    float theta = theta_p[0];

    // W = skew(w)
    float W[9]  = { 0.f, -wz,  wy,
                    wz,  0.f, -wx,
                   -wy,  wx,  0.f };
    float W2[9];
    for (int i = 0; i < 3; i++)
        for (int j = 0; j < 3; j++) {
            float acc = 0.f;
            for (int k = 0; k < 3; k++) acc += W[i*3+k] * W[k*3+j];
            W2[i*3+j] = acc;
        }

    float s = sinf(theta), c = cosf(theta);
    float omc = 1.f - c;       // 1 - cos
    float tms = theta - s;     // theta - sin

    // R = I + s*W + (1-c)*W^2 ; V = I*theta + (1-c)*W + (theta-s)*W^2 ; t = V v
    float t3[3];
    for (int i = 0; i < 3; i++) {
        float Vi[3];
        for (int j = 0; j < 3; j++) {
            float I = (i == j) ? 1.f : 0.f;
            float R = I + s * W[i*3+j] + omc * W2[i*3+j];
            Vi[j]   = I * theta + omc * W[i*3+j] + tms * W2[i*3+j];
            g_E[i*4 + j] = R;
        }
        t3[i] = Vi[0]*v[0] + Vi[1]*v[1] + Vi[2]*v[2];
        g_E[i*4 + 3] = t3[i];
    }
    g_E[12] = 0.f; g_E[13] = 0.f; g_E[14] = 0.f; g_E[15] = 1.f;
}

__global__ __launch_bounds__(256)
void transform_kernel(const float4* __restrict__ x,
                      float4* __restrict__ out, int B) {
    int b = blockIdx.x * blockDim.x + threadIdx.x;
    if (b >= B) return;

    // Uniform broadcast load of E (L2-resident after setup kernel)
    float e00 = g_E[0],  e01 = g_E[1],  e02 = g_E[2],  e03 = g_E[3];
    float e10 = g_E[4],  e11 = g_E[5],  e12 = g_E[6],  e13 = g_E[7];
    float e20 = g_E[8],  e21 = g_E[9],  e22 = g_E[10], e23 = g_E[11];

    const float4* xm = x + (size_t)b * 4;
    float4 r0 = xm[0];
    float4 r1 = xm[1];
    float4 r2 = xm[2];
    float4 r3 = xm[3];

    float4 o0, o1, o2;
    o0.x = e00*r0.x + e01*r1.x + e02*r2.x + e03*r3.x;
    o0.y = e00*r0.y + e01*r1.y + e02*r2.y + e03*r3.y;
    o0.z = e00*r0.z + e01*r1.z + e02*r2.z + e03*r3.z;
    o0.w = e00*r0.w + e01*r1.w + e02*r2.w + e03*r3.w;

    o1.x = e10*r0.x + e11*r1.x + e12*r2.x + e13*r3.x;
    o1.y = e10*r0.y + e11*r1.y + e12*r2.y + e13*r3.y;
    o1.z = e10*r0.z + e11*r1.z + e12*r2.z + e13*r3.z;
    o1.w = e10*r0.w + e11*r1.w + e12*r2.w + e13*r3.w;

    o2.x = e20*r0.x + e21*r1.x + e22*r2.x + e23*r3.x;
    o2.y = e20*r0.y + e21*r1.y + e22*r2.y + e23*r3.y;
    o2.z = e20*r0.z + e21*r1.z + e22*r2.z + e23*r3.z;
    o2.w = e20*r0.w + e21*r1.w + e22*r2.w + e23*r3.w;

    float4* om = out + (size_t)b * 4;
    om[0] = o0;
    om[1] = o1;
    om[2] = o2;
    om[3] = r3;  // bottom row of E is (0,0,0,1): out row 3 == x row 3 exactly
}

extern "C" void kernel_launch(void* const* d_in, const int* in_sizes, int n_in,
                              void* d_out, int out_size) {
    const float* w     = (const float*)d_in[0];
    const float* v     = (const float*)d_in[1];
    const float* theta = (const float*)d_in[2];
    const float* x     = (const float*)d_in[3];

    int B = in_sizes[3] / 16;  // number of 4x4 matrices

    setup_E_kernel<<<1, 32>>>(w, v, theta);

    const int TPB = 256;
    int grid = (B + TPB - 1) / TPB;
    transform_kernel<<<grid, TPB>>>((const float4*)x, (float4*)d_out, B);
}